// round 8
// baseline (speedup 1.0000x reference)
#include <cuda_runtime.h>
#include <cstdint>

typedef unsigned long long ull;
typedef unsigned int u32;

#define L 512
#define H 1024
#define C 2

// Scratch: ap/bp stored as packed f16x2 (word = 2 consecutive h)
__device__ u32 g_aph[L * H / 2];   // tanh-arg A part + b1, f16x2
__device__ u32 g_bph[L * H / 2];   // tanh-arg B part, f16x2
__device__ float g_f[L * L * C];   // unsymmetrized logits f[i][j][c]

// ---- helpers ----
__device__ __forceinline__ u32 packh(float lo, float hi) {
    u32 r;
    asm("cvt.rn.f16x2.f32 %0, %1, %2;" : "=r"(r) : "f"(hi), "f"(lo));
    return r;
}
__device__ __forceinline__ u32 hadd2(u32 a, u32 b) {
    u32 r;
    asm("add.rn.f16x2 %0, %1, %2;" : "=r"(r) : "r"(a), "r"(b));
    return r;
}
__device__ __forceinline__ u32 tanh2h(u32 x) {
    u32 r;
    asm("tanh.approx.f16x2 %0, %1;" : "=r"(r) : "r"(x));
    return r;
}
__device__ __forceinline__ u32 to_tf32(float f) {
    u32 r;
    asm("cvt.rna.tf32.f32 %0, %1;" : "=r"(r) : "f"(f));
    return r;
}
__device__ __forceinline__ void mma_tf32(float c[4], u32 a0, u32 a1, u32 a2, u32 a3,
                                         u32 b0, u32 b1) {
    asm("mma.sync.aligned.m16n8k8.row.col.f32.tf32.tf32.f32 "
        "{%0,%1,%2,%3}, {%4,%5,%6,%7}, {%8,%9}, {%0,%1,%2,%3};"
        : "+f"(c[0]), "+f"(c[1]), "+f"(c[2]), "+f"(c[3])
        : "r"(a0), "r"(a1), "r"(a2), "r"(a3), "r"(b0), "r"(b1));
}
__device__ __forceinline__ void mma_f16(float c[4], u32 a0, u32 a1, u32 a2, u32 a3,
                                        u32 b0, u32 b1) {
    asm("mma.sync.aligned.m16n8k16.row.col.f32.f16.f16.f32 "
        "{%0,%1,%2,%3}, {%4,%5,%6,%7}, {%8,%9}, {%0,%1,%2,%3};"
        : "+f"(c[0]), "+f"(c[1]), "+f"(c[2]), "+f"(c[3])
        : "r"(a0), "r"(a1), "r"(a2), "r"(a3), "r"(b0), "r"(b1));
}

// ============================================================
// Kernel 1: tf32 MMA GEMM (R5 mainloop, measured 41.7us).
// 128-thread CTAs, tile 32l x 32o, BOTH ap/bp outputs, grid 512.
// Epilogue now packs results to f16x2 for k2.
// ============================================================
#define G_BM 32
#define G_BN 32
#define G_KC 32
#define G_PAD 36

__global__ __launch_bounds__(128) void k1_mma(const float* __restrict__ x,
                                              const float* __restrict__ W1,
                                              const float* __restrict__ b1) {
    __shared__ __align__(16) float xs[2][G_BM][G_PAD];
    __shared__ __align__(16) float was[2][G_BN][G_PAD];
    __shared__ __align__(16) float wbs[2][G_BN][G_PAD];

    const int t = threadIdx.x;
    const int lane = t & 31;
    const int wid = t >> 5;
    const int gid = lane >> 2;
    const int tig = lane & 3;
    const int wm = wid & 1;
    const int wn = wid >> 1;
    const int lblk = blockIdx.y * G_BM;
    const int oblk = blockIdx.x * G_BN;

    const int r = t >> 2;
    const int c40 = (t & 3) * 8;

    const float* xp = x + (lblk + r) * H + c40;
    const float* wp = W1 + (oblk + r) * (2 * H) + c40;

    float accA[2][4], accB[2][4];
#pragma unroll
    for (int na = 0; na < 2; na++)
#pragma unroll
        for (int q = 0; q < 4; q++) { accA[na][q] = 0.f; accB[na][q] = 0.f; }

    float4 rx[2], rwa[2], rwb[2];

#define LOAD_GLB(kb)                                   \
    do {                                               \
        rx[0]  = *(const float4*)(xp + (kb));          \
        rx[1]  = *(const float4*)(xp + (kb) + 4);      \
        rwa[0] = *(const float4*)(wp + (kb));          \
        rwa[1] = *(const float4*)(wp + (kb) + 4);      \
        rwb[0] = *(const float4*)(wp + (kb) + H);      \
        rwb[1] = *(const float4*)(wp + (kb) + H + 4);  \
    } while (0)

#define STORE_TILES(bf)                                                  \
    do {                                                                 \
        _Pragma("unroll")                                                \
        for (int q = 0; q < 2; q++) {                                    \
            const int c4 = c40 + q * 4;                                  \
            uint4 v;                                                     \
            v.x = to_tf32(rx[q].x);  v.y = to_tf32(rx[q].y);             \
            v.z = to_tf32(rx[q].z);  v.w = to_tf32(rx[q].w);             \
            *(uint4*)&xs[bf][r][c4] = v;                                 \
            v.x = to_tf32(rwa[q].x); v.y = to_tf32(rwa[q].y);            \
            v.z = to_tf32(rwa[q].z); v.w = to_tf32(rwa[q].w);            \
            *(uint4*)&was[bf][r][c4] = v;                                \
            v.x = to_tf32(rwb[q].x); v.y = to_tf32(rwb[q].y);            \
            v.z = to_tf32(rwb[q].z); v.w = to_tf32(rwb[q].w);            \
            *(uint4*)&wbs[bf][r][c4] = v;                                \
        }                                                                \
    } while (0)

#define COMPUTE(bf)                                                      \
    do {                                                                 \
        _Pragma("unroll")                                                \
        for (int ks = 0; ks < 4; ks++) {                                 \
            const int k0 = ks * 8;                                       \
            const int ra0 = wm * 16 + gid;                               \
            u32 a0 = *(const u32*)&xs[bf][ra0][k0 + tig];                \
            u32 a1 = *(const u32*)&xs[bf][ra0 + 8][k0 + tig];            \
            u32 a2 = *(const u32*)&xs[bf][ra0][k0 + tig + 4];            \
            u32 a3 = *(const u32*)&xs[bf][ra0 + 8][k0 + tig + 4];        \
            _Pragma("unroll")                                            \
            for (int na = 0; na < 2; na++) {                             \
                const int rn = wn * 16 + na * 8 + gid;                   \
                u32 ba0 = *(const u32*)&was[bf][rn][k0 + tig];           \
                u32 ba1 = *(const u32*)&was[bf][rn][k0 + tig + 4];       \
                u32 bb0 = *(const u32*)&wbs[bf][rn][k0 + tig];           \
                u32 bb1 = *(const u32*)&wbs[bf][rn][k0 + tig + 4];       \
                mma_tf32(accA[na], a0, a1, a2, a3, ba0, ba1);            \
                mma_tf32(accB[na], a0, a1, a2, a3, bb0, bb1);            \
            }                                                            \
        }                                                                \
    } while (0)

    LOAD_GLB(0);
    STORE_TILES(0);
    __syncthreads();

    int buf = 0;
#pragma unroll 1
    for (int it = 0; it < H / G_KC; it++) {
        if (it < H / G_KC - 1) LOAD_GLB((it + 1) * G_KC);
        COMPUTE(buf);
        if (it < H / G_KC - 1) {
            STORE_TILES(buf ^ 1);
            __syncthreads();
            buf ^= 1;
        }
    }

    // epilogue: pack to f16x2. col, col+1 form one h-pair word.
    const int row0 = lblk + wm * 16 + gid;
#pragma unroll
    for (int na = 0; na < 2; na++) {
        const int col = oblk + wn * 16 + na * 8 + tig * 2;
        const int wi = col >> 1;
        const float2 bv = *(const float2*)&b1[col];
        g_aph[row0 * (H / 2) + wi] = packh(accA[na][0] + bv.x, accA[na][1] + bv.y);
        g_aph[(row0 + 8) * (H / 2) + wi] = packh(accA[na][2] + bv.x, accA[na][3] + bv.y);
        g_bph[row0 * (H / 2) + wi] = packh(accB[na][0], accB[na][1]);
        g_bph[(row0 + 8) * (H / 2) + wi] = packh(accB[na][2], accB[na][3]);
    }
#undef LOAD_GLB
#undef STORE_TILES
#undef COMPUTE
}

// ============================================================
// Kernel 2: f[i,j,c] = sum_h tanh(ap[j,h]+bp[i,h]) * W2[c,h]
// via m16n8k16 f16 MMA: tanh.f16x2 output IS the A-fragment.
// CTA: 8 i x 64 j, 8 warps (1 i each), h chunk 64. grid (8,64).
// ============================================================
#define Q_TJ 64
#define Q_TI 8
#define Q_HC 64
#define Q_PAD 36

__global__ __launch_bounds__(256) void k2_mma(const float* __restrict__ W2) {
    __shared__ u32 aph[Q_TJ][Q_PAD];   // f16x2 words of ap (j rows)
    __shared__ u32 bph[Q_TI][Q_PAD];   // f16x2 words of bp (i rows)
    __shared__ u32 w2h[2][Q_PAD];      // f16x2 words of W2

    const int t = threadIdx.x;
    const int lane = t & 31;
    const int wid = t >> 5;
    const int gid = lane >> 2;
    const int tig = lane & 3;
    const int jblk = blockIdx.x * Q_TJ;
    const int iblk = blockIdx.y * Q_TI;
    const int i = iblk + wid;          // one i per warp

    float acc[4][4];
#pragma unroll
    for (int jt = 0; jt < 4; jt++)
#pragma unroll
        for (int q = 0; q < 4; q++) acc[jt][q] = 0.f;

    const int lrow = t & 63;           // aph row
    const int lq = (t >> 6) * 8;       // word base (0,8,16,24)

    for (int hb = 0; hb < H; hb += Q_HC) {
        const int hpb = hb >> 1;
        // aph: 64 rows x 32 words
        *(uint4*)&aph[lrow][lq] =
            *(const uint4*)&g_aph[(jblk + lrow) * (H / 2) + hpb + lq];
        *(uint4*)&aph[lrow][lq + 4] =
            *(const uint4*)&g_aph[(jblk + lrow) * (H / 2) + hpb + lq + 4];
        // bph: 8 rows x 32 words (t < 64)
        if (t < 64) {
            const int rr = t & 7, q4 = (t >> 3) * 4;
            *(uint4*)&bph[rr][q4] =
                *(const uint4*)&g_bph[(iblk + rr) * (H / 2) + hpb + q4];
        } else if (t < 128) {
            // w2h: pack from f32 (2 x 32 words)
            const int idx = t - 64;
            const int cc = idx >> 5, q = idx & 31;
            const float2 w = *(const float2*)&W2[cc * H + hb + q * 2];
            w2h[cc][q] = packh(w.x, w.y);
        }
        __syncthreads();

#pragma unroll
        for (int kc = 0; kc < 4; kc++) {
            const int kw = kc * 8;
            u32 b0 = 0, b1v = 0;
            if (gid < 2) {
                b0 = w2h[gid][kw + tig];
                b1v = w2h[gid][kw + tig + 4];
            }
            const u32 bp0 = bph[wid][kw + tig];
            const u32 bp1 = bph[wid][kw + tig + 4];
#pragma unroll
            for (int jt = 0; jt < 4; jt++) {
                const int rr = jt * 16 + gid;
                u32 t0 = tanh2h(hadd2(aph[rr][kw + tig], bp0));
                u32 t1 = tanh2h(hadd2(aph[rr + 8][kw + tig], bp0));
                u32 t2 = tanh2h(hadd2(aph[rr][kw + tig + 4], bp1));
                u32 t3 = tanh2h(hadd2(aph[rr + 8][kw + tig + 4], bp1));
                mma_f16(acc[jt], t0, t1, t2, t3, b0, b1v);
            }
        }
        __syncthreads();
    }

    // epilogue: tig==0 lanes hold cols 0,1 (= c channels) as f32 pairs
    if (tig == 0) {
#pragma unroll
        for (int jt = 0; jt < 4; jt++) {
            const int j = jblk + jt * 16 + gid;
            float2 v0; v0.x = acc[jt][0]; v0.y = acc[jt][1];
            float2 v1; v1.x = acc[jt][2]; v1.y = acc[jt][3];
            *(float2*)&g_f[(i * L + j) * 2] = v0;
            *(float2*)&g_f[(i * L + j + 8) * 2] = v1;
        }
    }
}

// ============================================================
// Kernel 3: out[i,j,c] = 0.5*(f[i,j,c] + f[j,i,c]) + b2[c]
// ============================================================
__global__ __launch_bounds__(256) void k3_sym(const float* __restrict__ b2,
                                              float* __restrict__ out) {
    const int idx = blockIdx.x * 256 + threadIdx.x;
    const int i = idx >> 9;
    const int j = idx & (L - 1);
    const float2 fij = *(const float2*)&g_f[idx * 2];
    const float2 fji = *(const float2*)&g_f[((j << 9) | i) * 2];
    float2 r;
    r.x = (fij.x + fji.x) * 0.5f + b2[0];
    r.y = (fij.y + fji.y) * 0.5f + b2[1];
    *(float2*)&out[idx * 2] = r;
}

extern "C" void kernel_launch(void* const* d_in, const int* in_sizes, int n_in,
                              void* d_out, int out_size) {
    const float* x  = (const float*)d_in[0];
    const float* W1 = (const float*)d_in[1];
    const float* b1 = (const float*)d_in[2];
    const float* W2 = (const float*)d_in[3];
    const float* b2 = (const float*)d_in[4];
    float* out = (float*)d_out;

    k1_mma<<<dim3(H / G_BN, L / G_BM), 128>>>(x, W1, b1);
    k2_mma<<<dim3(L / Q_TJ, L / Q_TI), 256>>>(W2);
    k3_sym<<<(L * L) / 256, 256>>>(b2, out);
}

// round 9
// speedup vs baseline: 1.2147x; 1.2147x over previous
#include <cuda_runtime.h>
#include <cstdint>

typedef unsigned long long ull;
typedef unsigned int u32;

#define L 512
#define H 1024
#define C 2

// Scratch
__device__ float g_ap[L * H];      // a_proj + b1, [l][o]
__device__ float g_bp[L * H];      // b_proj,      [l][o]
__device__ float g_f[L * L * C];   // unsymmetrized logits f[i][j][c]

// ---- packed f32x2 helpers ----
__device__ __forceinline__ ull ffma2(ull a, ull b, ull c) {
    ull d;
    asm("fma.rn.f32x2 %0, %1, %2, %3;" : "=l"(d) : "l"(a), "l"(b), "l"(c));
    return d;
}
__device__ __forceinline__ ull fadd2(ull a, ull b) {
    ull d;
    asm("add.rn.f32x2 %0, %1, %2;" : "=l"(d) : "l"(a), "l"(b));
    return d;
}
__device__ __forceinline__ float2 u2f2(ull u) {
    float2 v;
    asm("mov.b64 {%0, %1}, %2;" : "=f"(v.x), "=f"(v.y) : "l"(u));
    return v;
}
__device__ __forceinline__ ull tanh2(ull x) {
    ull r;
    asm("{\n\t"
        ".reg .f32 lo, hi;\n\t"
        "mov.b64 {lo, hi}, %1;\n\t"
        "tanh.approx.f32 lo, lo;\n\t"
        "tanh.approx.f32 hi, hi;\n\t"
        "mov.b64 %0, {lo, hi};\n\t"
        "}" : "=l"(r) : "l"(x));
    return r;
}
__device__ __forceinline__ u32 to_tf32(float f) {
    u32 r;
    asm("cvt.rna.tf32.f32 %0, %1;" : "=r"(r) : "f"(f));
    return r;
}
__device__ __forceinline__ u32 smem_u32(const void* p) {
    u32 a;
    asm("{ .reg .u64 tmp; cvta.to.shared.u64 tmp, %1; cvt.u32.u64 %0, tmp; }"
        : "=r"(a) : "l"(p));
    return a;
}
__device__ __forceinline__ void mma_tf32(float c[4], u32 a0, u32 a1, u32 a2, u32 a3,
                                         u32 b0, u32 b1) {
    asm("mma.sync.aligned.m16n8k8.row.col.f32.tf32.tf32.f32 "
        "{%0,%1,%2,%3}, {%4,%5,%6,%7}, {%8,%9}, {%0,%1,%2,%3};"
        : "+f"(c[0]), "+f"(c[1]), "+f"(c[2]), "+f"(c[3])
        : "r"(a0), "r"(a1), "r"(a2), "r"(a3), "r"(b0), "r"(b1));
}
__device__ __forceinline__ void ldsm_x4(u32& r0, u32& r1, u32& r2, u32& r3, u32 addr) {
    asm volatile("ldmatrix.sync.aligned.m8n8.x4.shared.b16 {%0,%1,%2,%3}, [%4];"
                 : "=r"(r0), "=r"(r1), "=r"(r2), "=r"(r3) : "r"(addr));
}

// ============================================================
// Kernel 1: tf32 MMA GEMM, ldmatrix fragments, CTA 64l x 64o,
// 256 thr / 8 warps (warp grid 2m x 4n; warp tile m32 x n16 x
// {ap,bp}); double-buffered pad-36 smem; grid 16x8 = one wave.
// ============================================================
#define B_PAD 36
#define TILE_SZ (64 * B_PAD)          // words per 64x32 tile

__global__ __launch_bounds__(256) void k1_mma(const float* __restrict__ x,
                                              const float* __restrict__ W1,
                                              const float* __restrict__ b1) {
    extern __shared__ float sm[];
    const u32 smb = smem_u32(sm);

    const int t = threadIdx.x;
    const int lane = t & 31;
    const int wid = t >> 5;
    const int gid = lane >> 2;
    const int tig = lane & 3;
    const int wm = wid & 1;           // 2 m-warps (32 rows each)
    const int wn = wid >> 1;          // 4 n-warps (16 cols each)
    const int oblk = blockIdx.x * 64;
    const int lblk = blockIdx.y * 64;

    // loader: rows r, r+32; 16B chunk c4
    const int r = t >> 3;
    const int c4 = (t & 7) * 4;
    const float* xp = x + (lblk + r) * H + c4;
    const float* wp = W1 + (oblk + r) * (2 * H) + c4;

    // ldmatrix per-lane offsets (word units within a buffer)
    const int q = lane >> 3, l7 = lane & 7;
    const u32 a_off = (u32)((wm * 32 + ((q & 1) << 3) + l7) * B_PAD + ((q >> 1) << 2));
    const u32 b_off = (u32)(((q >> 1) + 1) * TILE_SZ +
                            (wn * 16 + l7) * B_PAD + ((q & 1) << 2));

    float accA[2][2][4], accB[2][2][4];
#pragma unroll
    for (int mi = 0; mi < 2; mi++)
#pragma unroll
        for (int na = 0; na < 2; na++)
#pragma unroll
            for (int k = 0; k < 4; k++) { accA[mi][na][k] = 0.f; accB[mi][na][k] = 0.f; }

    float4 rx[2], rwa[2], rwb[2];

#define LOAD_GLB(kb)                                        \
    do {                                                    \
        rx[0]  = *(const float4*)(xp + (kb));               \
        rx[1]  = *(const float4*)(xp + (kb) + 32 * H);      \
        rwa[0] = *(const float4*)(wp + (kb));               \
        rwa[1] = *(const float4*)(wp + (kb) + 64 * H);      \
        rwb[0] = *(const float4*)(wp + (kb) + H);           \
        rwb[1] = *(const float4*)(wp + (kb) + 65 * H);      \
    } while (0)

#define CVT4(dst, v)                                        \
    do {                                                    \
        uint4 _u;                                           \
        _u.x = to_tf32((v).x); _u.y = to_tf32((v).y);       \
        _u.z = to_tf32((v).z); _u.w = to_tf32((v).w);       \
        *(uint4*)(dst) = _u;                                \
    } while (0)

#define STORE_TILES(bf)                                                    \
    do {                                                                   \
        const u32 wb = (bf) ? 3u * TILE_SZ : 0u;                           \
        CVT4(&sm[wb + r * B_PAD + c4], rx[0]);                             \
        CVT4(&sm[wb + (r + 32) * B_PAD + c4], rx[1]);                      \
        CVT4(&sm[wb + TILE_SZ + r * B_PAD + c4], rwa[0]);                  \
        CVT4(&sm[wb + TILE_SZ + (r + 32) * B_PAD + c4], rwa[1]);           \
        CVT4(&sm[wb + 2 * TILE_SZ + r * B_PAD + c4], rwb[0]);              \
        CVT4(&sm[wb + 2 * TILE_SZ + (r + 32) * B_PAD + c4], rwb[1]);       \
    } while (0)

#define COMPUTE(bf)                                                        \
    do {                                                                   \
        const u32 abase = smb + ((bf) ? 3u * TILE_SZ : 0u) * 4 + a_off * 4;\
        const u32 bbase = smb + ((bf) ? 3u * TILE_SZ : 0u) * 4 + b_off * 4;\
        _Pragma("unroll")                                                  \
        for (int ks = 0; ks < 4; ks++) {                                   \
            u32 A[2][4];                                                   \
            _Pragma("unroll")                                              \
            for (int mi = 0; mi < 2; mi++)                                 \
                ldsm_x4(A[mi][0], A[mi][1], A[mi][2], A[mi][3],            \
                        abase + (mi * 16 * B_PAD + ks * 8) * 4);           \
            _Pragma("unroll")                                              \
            for (int na = 0; na < 2; na++) {                               \
                u32 B0, B1, B2, B3;                                        \
                ldsm_x4(B0, B1, B2, B3,                                    \
                        bbase + (na * 8 * B_PAD + ks * 8) * 4);            \
                _Pragma("unroll")                                          \
                for (int mi = 0; mi < 2; mi++) {                           \
                    mma_tf32(accA[mi][na], A[mi][0], A[mi][1], A[mi][2],   \
                             A[mi][3], B0, B1);                            \
                    mma_tf32(accB[mi][na], A[mi][0], A[mi][1], A[mi][2],   \
                             A[mi][3], B2, B3);                            \
                }                                                          \
            }                                                              \
        }                                                                  \
    } while (0)

    LOAD_GLB(0);
    STORE_TILES(0);
    __syncthreads();

    int buf = 0;
#pragma unroll 1
    for (int it = 0; it < H / 32; it++) {
        if (it < H / 32 - 1) LOAD_GLB((it + 1) * 32);
        COMPUTE(buf);
        if (it < H / 32 - 1) {
            STORE_TILES(buf ^ 1);
            __syncthreads();
            buf ^= 1;
        }
    }

    // epilogue: c0=(g,2t) c1=(g,2t+1) c2=(g+8,2t) c3=(g+8,2t+1)
#pragma unroll
    for (int mi = 0; mi < 2; mi++) {
        const int row0 = lblk + wm * 32 + mi * 16 + gid;
#pragma unroll
        for (int na = 0; na < 2; na++) {
            const int col = oblk + wn * 16 + na * 8 + tig * 2;
            const float2 bv = *(const float2*)&b1[col];
            float2 v;
            v.x = accA[mi][na][0] + bv.x; v.y = accA[mi][na][1] + bv.y;
            *(float2*)&g_ap[row0 * H + col] = v;
            v.x = accA[mi][na][2] + bv.x; v.y = accA[mi][na][3] + bv.y;
            *(float2*)&g_ap[(row0 + 8) * H + col] = v;
            v.x = accB[mi][na][0]; v.y = accB[mi][na][1];
            *(float2*)&g_bp[row0 * H + col] = v;
            v.x = accB[mi][na][2]; v.y = accB[mi][na][3];
            *(float2*)&g_bp[(row0 + 8) * H + col] = v;
        }
    }
#undef LOAD_GLB
#undef CVT4
#undef STORE_TILES
#undef COMPUTE
}

#define K1_SMEM (2 * 3 * TILE_SZ * 4)   // 55296 bytes

// ============================================================
// Kernel 2: f[i,j,c] = sum_h tanh(ap[j,h] + bp[i,h]) * W2[c,h]
// Tile 16i x 32j, 256 threads (1i x 2j each), HC=64. MUFU-bound.
// (R3 version — best measured: ~68.5us.)
// ============================================================
#define P_TI 16
#define P_TJ 32
#define P_HC 64
#define P_PAD 66

__global__ __launch_bounds__(256) void k2_pair(const float* __restrict__ W2) {
    __shared__ __align__(16) float as[P_TJ][P_PAD];   // ap rows (j)
    __shared__ __align__(16) float bs[P_TI][P_PAD];   // bp rows (i)
    __shared__ __align__(16) float w2s[2][P_HC];

    const int t = threadIdx.x;
    const int tx = t & 15;   // j
    const int ty = t >> 4;   // i (16 values)
    const int jblk = blockIdx.x * P_TJ;
    const int iblk = blockIdx.y * P_TI;

    ull acc[2][2];
    acc[0][0] = acc[0][1] = acc[1][0] = acc[1][1] = 0ull;

    for (int hb = 0; hb < H; hb += P_HC) {
#pragma unroll
        for (int q = 0; q < 4; q++) {
            int idx = t + q * 256;
            int rr = idx >> 5, c = (idx & 31) * 2;
            *(float2*)&as[rr][c] = *(const float2*)&g_ap[(jblk + rr) * H + hb + c];
        }
#pragma unroll
        for (int q = 0; q < 2; q++) {
            int idx = t + q * 256;
            int rr = idx >> 5, c = (idx & 31) * 2;
            *(float2*)&bs[rr][c] = *(const float2*)&g_bp[(iblk + rr) * H + hb + c];
        }
        if (t < 64) {
            int rr = t >> 5, c = (t & 31) * 2;
            *(float2*)&w2s[rr][c] = *(const float2*)&W2[rr * H + hb + c];
        }
        __syncthreads();

#pragma unroll 16
        for (int hp = 0; hp < P_HC / 2; hp++) {
            ull a0 = *(const ull*)&as[tx][hp * 2];
            ull a1 = *(const ull*)&as[tx + 16][hp * 2];
            ull b0 = *(const ull*)&bs[ty][hp * 2];
            ull w0 = *(const ull*)&w2s[0][hp * 2];
            ull w1 = *(const ull*)&w2s[1][hp * 2];

            ull t0 = tanh2(fadd2(a0, b0));
            ull t1 = tanh2(fadd2(a1, b0));

            acc[0][0] = ffma2(t0, w0, acc[0][0]);
            acc[0][1] = ffma2(t0, w1, acc[0][1]);
            acc[1][0] = ffma2(t1, w0, acc[1][0]);
            acc[1][1] = ffma2(t1, w1, acc[1][1]);
        }
        __syncthreads();
    }

    const int i = iblk + ty;
#pragma unroll
    for (int jv = 0; jv < 2; jv++) {
        const int j = jblk + tx + jv * 16;
        float2 s0 = u2f2(acc[jv][0]);
        float2 s1 = u2f2(acc[jv][1]);
        float2 o;
        o.x = s0.x + s0.y;
        o.y = s1.x + s1.y;
        *(float2*)&g_f[(i * L + j) * 2] = o;
    }
}

// ============================================================
// Kernel 3: out[i,j,c] = 0.5*(f[i,j,c] + f[j,i,c]) + b2[c]
// ============================================================
__global__ __launch_bounds__(256) void k3_sym(const float* __restrict__ b2,
                                              float* __restrict__ out) {
    const int idx = blockIdx.x * 256 + threadIdx.x;
    const int i = idx >> 9;
    const int j = idx & (L - 1);
    const float2 fij = *(const float2*)&g_f[idx * 2];
    const float2 fji = *(const float2*)&g_f[((j << 9) | i) * 2];
    float2 r;
    r.x = (fij.x + fji.x) * 0.5f + b2[0];
    r.y = (fij.y + fji.y) * 0.5f + b2[1];
    *(float2*)&out[idx * 2] = r;
}

extern "C" void kernel_launch(void* const* d_in, const int* in_sizes, int n_in,
                              void* d_out, int out_size) {
    const float* x  = (const float*)d_in[0];
    const float* W1 = (const float*)d_in[1];
    const float* b1 = (const float*)d_in[2];
    const float* W2 = (const float*)d_in[3];
    const float* b2 = (const float*)d_in[4];
    float* out = (float*)d_out;

    cudaFuncSetAttribute(k1_mma, cudaFuncAttributeMaxDynamicSharedMemorySize,
                         K1_SMEM);

    k1_mma<<<dim3(H / 64, L / 64), 256, K1_SMEM>>>(x, W1, b1);
    k2_pair<<<dim3(L / P_TJ, L / P_TI), 256>>>(W2);
    k3_sym<<<(L * L) / 256, 256>>>(b2, out);
}

// round 10
// speedup vs baseline: 1.2515x; 1.0303x over previous
#include <cuda_runtime.h>
#include <cstdint>

typedef unsigned long long ull;
typedef unsigned int u32;

#define L 512
#define H 1024
#define C 2

// Scratch
__device__ float g_ap[L * H];      // a_proj + b1, [l][o]
__device__ float g_bp[L * H];      // b_proj,      [l][o]
__device__ float g_f[L * L * C];   // unsymmetrized logits f[i][j][c]

// ---- packed f32x2 helpers ----
__device__ __forceinline__ ull ffma2(ull a, ull b, ull c) {
    ull d;
    asm("fma.rn.f32x2 %0, %1, %2, %3;" : "=l"(d) : "l"(a), "l"(b), "l"(c));
    return d;
}
__device__ __forceinline__ ull fadd2(ull a, ull b) {
    ull d;
    asm("add.rn.f32x2 %0, %1, %2;" : "=l"(d) : "l"(a), "l"(b));
    return d;
}
__device__ __forceinline__ float2 u2f2(ull u) {
    float2 v;
    asm("mov.b64 {%0, %1}, %2;" : "=f"(v.x), "=f"(v.y) : "l"(u));
    return v;
}
__device__ __forceinline__ ull tanh2(ull x) {
    ull r;
    asm("{\n\t"
        ".reg .f32 lo, hi;\n\t"
        "mov.b64 {lo, hi}, %1;\n\t"
        "tanh.approx.f32 lo, lo;\n\t"
        "tanh.approx.f32 hi, hi;\n\t"
        "mov.b64 %0, {lo, hi};\n\t"
        "}" : "=l"(r) : "l"(x));
    return r;
}
__device__ __forceinline__ u32 smem_u32(const void* p) {
    u32 a;
    asm("{ .reg .u64 tmp; cvta.to.shared.u64 tmp, %1; cvt.u32.u64 %0, tmp; }"
        : "=r"(a) : "l"(p));
    return a;
}
__device__ __forceinline__ void mma_tf32(float c[4], u32 a0, u32 a1, u32 a2, u32 a3,
                                         u32 b0, u32 b1) {
    asm("mma.sync.aligned.m16n8k8.row.col.f32.tf32.tf32.f32 "
        "{%0,%1,%2,%3}, {%4,%5,%6,%7}, {%8,%9}, {%0,%1,%2,%3};"
        : "+f"(c[0]), "+f"(c[1]), "+f"(c[2]), "+f"(c[3])
        : "r"(a0), "r"(a1), "r"(a2), "r"(a3), "r"(b0), "r"(b1));
}
__device__ __forceinline__ void ldsm_x4(u32& r0, u32& r1, u32& r2, u32& r3, u32 addr) {
    asm volatile("ldmatrix.sync.aligned.m8n8.x4.shared.b16 {%0,%1,%2,%3}, [%4];"
                 : "=r"(r0), "=r"(r1), "=r"(r2), "=r"(r3) : "r"(addr));
}
__device__ __forceinline__ void cp16(u32 dst, const void* src) {
    asm volatile("cp.async.ca.shared.global [%0], [%1], 16;"
                 :: "r"(dst), "l"(src) : "memory");
}
#define CP_COMMIT() asm volatile("cp.async.commit_group;" ::: "memory")
#define CP_WAIT1()  asm volatile("cp.async.wait_group 1;" ::: "memory")

// ============================================================
// Kernel 1: tf32 MMA GEMM, cp.async 3-stage pipeline, ldmatrix
// fragments, NO tf32 cvt (raw f32 = truncation; HMMA ignores the
// low mantissa bits). CTA 128 thr, tile 64l x 32o, both ap/bp.
// Grid 32x8 = 256 CTAs -> ~2 CTAs/SM.
// ============================================================
#define B_PAD 36
#define S_WORDS (128 * B_PAD)        // A(64 rows) + WA(32) + WB(32), padded
#define K1_SMEM (3 * S_WORDS * 4)    // 55296 bytes

__global__ __launch_bounds__(128) void k1_mma(const float* __restrict__ x,
                                              const float* __restrict__ W1,
                                              const float* __restrict__ b1) {
    extern __shared__ float sm[];
    const u32 smb = smem_u32(sm);

    const int t = threadIdx.x;
    const int lane = t & 31;
    const int wid = t >> 5;
    const int gid = lane >> 2;
    const int tig = lane & 3;
    const int wm = wid & 1;           // 2 m-warps (32 rows each)
    const int wn = wid >> 1;          // 2 n-warps (16 cols each)
    const int oblk = blockIdx.x * 32;
    const int lblk = blockIdx.y * 64;

    // loader: base row r (0..15), 16B chunk c4; rows r+16q
    const int r = t >> 3;
    const int c4 = (t & 7) * 4;
    const float* xg = x + (lblk + r) * H + c4;
    const float* wg = W1 + (oblk + r) * (2 * H) + c4;

    // ldmatrix per-lane offsets (word units within a stage)
    const int q = lane >> 3, l7 = lane & 7;
    const u32 a_off = (u32)((wm * 32 + ((q & 1) << 3) + l7) * B_PAD + ((q >> 1) << 2));
    const u32 b_off = (u32)((64 + (q >> 1) * 32 + wn * 16 + l7) * B_PAD + ((q & 1) << 2));

    float accA[2][2][4], accB[2][2][4];
#pragma unroll
    for (int mi = 0; mi < 2; mi++)
#pragma unroll
        for (int na = 0; na < 2; na++)
#pragma unroll
            for (int k = 0; k < 4; k++) { accA[mi][na][k] = 0.f; accB[mi][na][k] = 0.f; }

#define PREFETCH(chunk)                                                     \
    do {                                                                    \
        const int kb = (chunk) * 32;                                        \
        const u32 sb = smb + ((chunk) % 3) * S_WORDS * 4;                   \
        _Pragma("unroll")                                                   \
        for (int qq = 0; qq < 4; qq++)                                      \
            cp16(sb + ((r + 16 * qq) * B_PAD + c4) * 4,                     \
                 xg + 16 * qq * H + kb);                                    \
        _Pragma("unroll")                                                   \
        for (int qq = 0; qq < 2; qq++) {                                    \
            cp16(sb + ((64 + r + 16 * qq) * B_PAD + c4) * 4,                \
                 wg + 16 * qq * (2 * H) + kb);                              \
            cp16(sb + ((96 + r + 16 * qq) * B_PAD + c4) * 4,                \
                 wg + 16 * qq * (2 * H) + kb + H);                          \
        }                                                                   \
    } while (0)

#define COMPUTE(stg)                                                        \
    do {                                                                    \
        const u32 abase = smb + (stg) * S_WORDS * 4 + a_off * 4;            \
        const u32 bbase = smb + (stg) * S_WORDS * 4 + b_off * 4;            \
        _Pragma("unroll")                                                   \
        for (int ks = 0; ks < 4; ks++) {                                    \
            u32 A[2][4];                                                    \
            _Pragma("unroll")                                               \
            for (int mi = 0; mi < 2; mi++)                                  \
                ldsm_x4(A[mi][0], A[mi][1], A[mi][2], A[mi][3],             \
                        abase + (mi * 16 * B_PAD + ks * 8) * 4);            \
            _Pragma("unroll")                                               \
            for (int na = 0; na < 2; na++) {                                \
                u32 B0, B1, B2, B3;                                         \
                ldsm_x4(B0, B1, B2, B3,                                     \
                        bbase + (na * 8 * B_PAD + ks * 8) * 4);             \
                _Pragma("unroll")                                           \
                for (int mi = 0; mi < 2; mi++) {                            \
                    mma_tf32(accA[mi][na], A[mi][0], A[mi][1], A[mi][2],    \
                             A[mi][3], B0, B1);                             \
                    mma_tf32(accB[mi][na], A[mi][0], A[mi][1], A[mi][2],    \
                             A[mi][3], B2, B3);                             \
                }                                                           \
            }                                                               \
        }                                                                   \
    } while (0)

    PREFETCH(0); CP_COMMIT();
    PREFETCH(1); CP_COMMIT();

#pragma unroll 1
    for (int it = 0; it < H / 32; it++) {
        CP_WAIT1();
        __syncthreads();
        if (it + 2 < H / 32) PREFETCH(it + 2);
        CP_COMMIT();
        COMPUTE(it % 3);
    }

    // epilogue: c0=(g,2t) c1=(g,2t+1) c2=(g+8,2t) c3=(g+8,2t+1)
#pragma unroll
    for (int mi = 0; mi < 2; mi++) {
        const int row0 = lblk + wm * 32 + mi * 16 + gid;
#pragma unroll
        for (int na = 0; na < 2; na++) {
            const int col = oblk + wn * 16 + na * 8 + tig * 2;
            const float2 bv = *(const float2*)&b1[col];
            float2 v;
            v.x = accA[mi][na][0] + bv.x; v.y = accA[mi][na][1] + bv.y;
            *(float2*)&g_ap[row0 * H + col] = v;
            v.x = accA[mi][na][2] + bv.x; v.y = accA[mi][na][3] + bv.y;
            *(float2*)&g_ap[(row0 + 8) * H + col] = v;
            v.x = accB[mi][na][0]; v.y = accB[mi][na][1];
            *(float2*)&g_bp[row0 * H + col] = v;
            v.x = accB[mi][na][2]; v.y = accB[mi][na][3];
            *(float2*)&g_bp[(row0 + 8) * H + col] = v;
        }
    }
#undef PREFETCH
#undef COMPUTE
}

// ============================================================
// Kernel 2: f[i,j,c] = sum_h tanh(ap[j,h] + bp[i,h]) * W2[c,h]
// Tile 16i x 32j, 256 threads (1i x 2j each), HC=64. MUFU-bound
// at its floor (R3 version, best measured).
// ============================================================
#define P_TI 16
#define P_TJ 32
#define P_HC 64
#define P_PAD 66

__global__ __launch_bounds__(256) void k2_pair(const float* __restrict__ W2) {
    __shared__ __align__(16) float as[P_TJ][P_PAD];   // ap rows (j)
    __shared__ __align__(16) float bs[P_TI][P_PAD];   // bp rows (i)
    __shared__ __align__(16) float w2s[2][P_HC];

    const int t = threadIdx.x;
    const int tx = t & 15;   // j
    const int ty = t >> 4;   // i (16 values)
    const int jblk = blockIdx.x * P_TJ;
    const int iblk = blockIdx.y * P_TI;

    ull acc[2][2];
    acc[0][0] = acc[0][1] = acc[1][0] = acc[1][1] = 0ull;

    for (int hb = 0; hb < H; hb += P_HC) {
#pragma unroll
        for (int qq = 0; qq < 4; qq++) {
            int idx = t + qq * 256;
            int rr = idx >> 5, c = (idx & 31) * 2;
            *(float2*)&as[rr][c] = *(const float2*)&g_ap[(jblk + rr) * H + hb + c];
        }
#pragma unroll
        for (int qq = 0; qq < 2; qq++) {
            int idx = t + qq * 256;
            int rr = idx >> 5, c = (idx & 31) * 2;
            *(float2*)&bs[rr][c] = *(const float2*)&g_bp[(iblk + rr) * H + hb + c];
        }
        if (t < 64) {
            int rr = t >> 5, c = (t & 31) * 2;
            *(float2*)&w2s[rr][c] = *(const float2*)&W2[rr * H + hb + c];
        }
        __syncthreads();

#pragma unroll 16
        for (int hp = 0; hp < P_HC / 2; hp++) {
            ull a0 = *(const ull*)&as[tx][hp * 2];
            ull a1 = *(const ull*)&as[tx + 16][hp * 2];
            ull b0 = *(const ull*)&bs[ty][hp * 2];
            ull w0 = *(const ull*)&w2s[0][hp * 2];
            ull w1 = *(const ull*)&w2s[1][hp * 2];

            ull t0 = tanh2(fadd2(a0, b0));
            ull t1 = tanh2(fadd2(a1, b0));

            acc[0][0] = ffma2(t0, w0, acc[0][0]);
            acc[0][1] = ffma2(t0, w1, acc[0][1]);
            acc[1][0] = ffma2(t1, w0, acc[1][0]);
            acc[1][1] = ffma2(t1, w1, acc[1][1]);
        }
        __syncthreads();
    }

    const int i = iblk + ty;
#pragma unroll
    for (int jv = 0; jv < 2; jv++) {
        const int j = jblk + tx + jv * 16;
        float2 s0 = u2f2(acc[jv][0]);
        float2 s1 = u2f2(acc[jv][1]);
        float2 o;
        o.x = s0.x + s0.y;
        o.y = s1.x + s1.y;
        *(float2*)&g_f[(i * L + j) * 2] = o;
    }
}

// ============================================================
// Kernel 3: out[i,j,c] = 0.5*(f[i,j,c] + f[j,i,c]) + b2[c]
// ============================================================
__global__ __launch_bounds__(256) void k3_sym(const float* __restrict__ b2,
                                              float* __restrict__ out) {
    const int idx = blockIdx.x * 256 + threadIdx.x;
    const int i = idx >> 9;
    const int j = idx & (L - 1);
    const float2 fij = *(const float2*)&g_f[idx * 2];
    const float2 fji = *(const float2*)&g_f[((j << 9) | i) * 2];
    float2 r;
    r.x = (fij.x + fji.x) * 0.5f + b2[0];
    r.y = (fij.y + fji.y) * 0.5f + b2[1];
    *(float2*)&out[idx * 2] = r;
}

extern "C" void kernel_launch(void* const* d_in, const int* in_sizes, int n_in,
                              void* d_out, int out_size) {
    const float* x  = (const float*)d_in[0];
    const float* W1 = (const float*)d_in[1];
    const float* b1 = (const float*)d_in[2];
    const float* W2 = (const float*)d_in[3];
    const float* b2 = (const float*)d_in[4];
    float* out = (float*)d_out;

    cudaFuncSetAttribute(k1_mma, cudaFuncAttributeMaxDynamicSharedMemorySize,
                         K1_SMEM);

    k1_mma<<<dim3(H / 32, L / 64), 128, K1_SMEM>>>(x, W1, b1);
    k2_pair<<<dim3(L / P_TJ, L / P_TI), 256>>>(W2);
    k3_sym<<<(L * L) / 256, 256>>>(b2, out);
}